// round 7
// baseline (speedup 1.0000x reference)
#include <cuda_runtime.h>
#include <cuda_bf16.h>

// firing_model: next = -prev + tanh(prev @ x) from prev = 0 -> identically
// zero trajectory (tanh(0) = 0 exactly in fp32; time_fomer never influences
// the returned rows). Output [499800, 69] is all zeros -> pure 138 MB
// zero-fill of d_out.
//
// CONVERGED (R7): six rounds established the roofline. Kernel time is pinned
// at ~20 us (~6.9 TB/s HBM3e write stream) across 1/2/4/8-store and v8-store
// geometries; total carries a fixed ~2.9 us graph-replay overhead. This is
// the best-measured configuration (R3): exact-cover, 2 contiguous streaming
// STG.128 per thread, 16 KB per block.

#define FILL_THREADS 256
#define F4_PER_THREAD 2   // each block covers FILL_THREADS * 2 float4s

__global__ void __launch_bounds__(FILL_THREADS)
firing_model_zero_fill2(float4* __restrict__ out, long long n4) {
    long long base = (long long)blockIdx.x * (FILL_THREADS * F4_PER_THREAD)
                   + threadIdx.x;
    const float4 z = make_float4(0.0f, 0.0f, 0.0f, 0.0f);

    long long i0 = base;
    long long i1 = base + FILL_THREADS;
    if (i0 < n4) __stcs(&out[i0], z);
    if (i1 < n4) __stcs(&out[i1], z);
}

__global__ void firing_model_zero_fill_tail(float* __restrict__ out,
                                            long long start, long long n) {
    long long i = start + (long long)blockIdx.x * blockDim.x + threadIdx.x;
    if (i < n) {
        out[i] = 0.0f;
    }
}

extern "C" void kernel_launch(void* const* d_in, const int* in_sizes, int n_in,
                              void* d_out, int out_size) {
    (void)d_in; (void)in_sizes; (void)n_in;

    float* out = (float*)d_out;
    long long n  = (long long)out_size;   // 34,486,200 floats expected
    long long n4 = n >> 2;                // 8,621,550 float4s (exact for this shape)
    long long tail_start = n4 << 2;

    if (n4 > 0) {
        long long per_block = FILL_THREADS * F4_PER_THREAD;
        long long blocks = (n4 + per_block - 1) / per_block;   // ~16,839
        firing_model_zero_fill2<<<(unsigned int)blocks, FILL_THREADS>>>(
            (float4*)out, n4);
    }
    if (tail_start < n) {  // not taken for this shape; defensive
        long long tail = n - tail_start;
        int blocks = (int)((tail + 255) / 256);
        firing_model_zero_fill_tail<<<blocks, 256>>>(out, tail_start, n);
    }
}

// round 8
// speedup vs baseline: 1.0170x; 1.0170x over previous
#include <cuda_runtime.h>
#include <cuda_bf16.h>

// firing_model: next = -prev + tanh(prev @ x) from prev = 0 -> identically
// zero trajectory (tanh(0) = 0 exactly in fp32; time_fomer never influences
// the returned rows). Output [499800, 69] is all zeros -> pure 138 MB
// zero-fill of d_out.
//
// CONVERGED (R8, final): 7 rounds mapped the landscape. Kernel time pinned
// at ~20 us (~6.9 TB/s HBM3e write stream; LTS cap is path-independent per
// B300 microarch, so TMA offers no alternative headroom) across 1/2/4/8-
// store and v8-store geometries. Total carries a fixed ~2.9 us graph-replay
// overhead. Best-measured configuration: exact-cover, 2 contiguous
// streaming STG.128 per thread, 16 KB per block.

#define FILL_THREADS 256
#define F4_PER_THREAD 2   // each block covers FILL_THREADS * 2 float4s

__global__ void __launch_bounds__(FILL_THREADS)
firing_model_zero_fill2(float4* __restrict__ out, long long n4) {
    long long base = (long long)blockIdx.x * (FILL_THREADS * F4_PER_THREAD)
                   + threadIdx.x;
    const float4 z = make_float4(0.0f, 0.0f, 0.0f, 0.0f);

    long long i0 = base;
    long long i1 = base + FILL_THREADS;
    if (i0 < n4) __stcs(&out[i0], z);
    if (i1 < n4) __stcs(&out[i1], z);
}

__global__ void firing_model_zero_fill_tail(float* __restrict__ out,
                                            long long start, long long n) {
    long long i = start + (long long)blockIdx.x * blockDim.x + threadIdx.x;
    if (i < n) {
        out[i] = 0.0f;
    }
}

extern "C" void kernel_launch(void* const* d_in, const int* in_sizes, int n_in,
                              void* d_out, int out_size) {
    (void)d_in; (void)in_sizes; (void)n_in;

    float* out = (float*)d_out;
    long long n  = (long long)out_size;   // 34,486,200 floats expected
    long long n4 = n >> 2;                // 8,621,550 float4s (exact for this shape)
    long long tail_start = n4 << 2;

    if (n4 > 0) {
        long long per_block = FILL_THREADS * F4_PER_THREAD;
        long long blocks = (n4 + per_block - 1) / per_block;   // ~16,839
        firing_model_zero_fill2<<<(unsigned int)blocks, FILL_THREADS>>>(
            (float4*)out, n4);
    }
    if (tail_start < n) {  // not taken for this shape; defensive
        long long tail = n - tail_start;
        int blocks = (int)((tail + 255) / 256);
        firing_model_zero_fill_tail<<<blocks, 256>>>(out, tail_start, n);
    }
}